// round 1
// baseline (speedup 1.0000x reference)
#include <cuda_runtime.h>
#include <math.h>

// Problem constants (B=4, S=1024 -> T=4096 tokens)
#define T 4096
#define H 1024
#define F 2048
#define E 8
#define NS 2
#define RTOT (NS * T + E * T) /* 40960 unified rows: 2 shared segments + 8 expert segments */

#define BM 64
#define BN 64
#define BK 32

// Scratch (allocation-free rule: __device__ globals)
__device__ float g_h[(size_t)RTOT * F]; // gelu(x@W1+b1) per (row-slot)
__device__ int g_perm[E * T];           // per-expert gathered token lists
__device__ int g_counts[E];

// ---------------------------------------------------------------------------
__global__ void zero_kernel(float* __restrict__ out) {
    int i = blockIdx.x * blockDim.x + threadIdx.x;
    if (i < T * H) out[i] = 0.0f;
    if (i < E) g_counts[i] = 0;
}

// ---------------------------------------------------------------------------
// Router: one block per token. logits = x@router_w + router_b; softmax is
// monotonic so top-k on logits == top-k on scores. Tie-break: lowest index
// first (strict > scan) matching jax.lax.top_k.
__global__ void router_kernel(const float* __restrict__ x,
                              const float* __restrict__ rw,
                              const float* __restrict__ rb) {
    int t = blockIdx.x;
    const float* xt = x + (size_t)t * H;
    float acc[E];
#pragma unroll
    for (int e = 0; e < E; e++) acc[e] = 0.0f;
    for (int h = threadIdx.x; h < H; h += blockDim.x) {
        float xv = xt[h];
#pragma unroll
        for (int e = 0; e < E; e++) acc[e] += xv * rw[h * E + e];
    }
    __shared__ float red[256];
    __shared__ float logits[E];
#pragma unroll
    for (int e = 0; e < E; e++) {
        red[threadIdx.x] = acc[e];
        __syncthreads();
        for (int s = 128; s > 0; s >>= 1) {
            if (threadIdx.x < s) red[threadIdx.x] += red[threadIdx.x + s];
            __syncthreads();
        }
        if (threadIdx.x == 0) logits[e] = red[0] + rb[e];
        __syncthreads();
    }
    if (threadIdx.x == 0) {
        int e0 = 0;
        float v0 = logits[0];
#pragma unroll
        for (int e = 1; e < E; e++)
            if (logits[e] > v0) { v0 = logits[e]; e0 = e; }
        int e1 = -1;
        float v1 = -3.0e38f;
#pragma unroll
        for (int e = 0; e < E; e++)
            if (e != e0 && logits[e] > v1) { v1 = logits[e]; e1 = e; }
        int p0 = atomicAdd(&g_counts[e0], 1);
        g_perm[e0 * T + p0] = t;
        int p1 = atomicAdd(&g_counts[e1], 1);
        g_perm[e1 * T + p1] = t;
    }
}

// ---------------------------------------------------------------------------
// Unified row space: rows [0, 2T) are shared experts (slot = row/T, token =
// row%T); rows [2T, 2T+E*T) are routed (expert e segment at 2T+e*T, first
// g_counts[e] rows valid via g_perm gather). Segment starts are BM-aligned so
// every block lies inside one expert.

__device__ __forceinline__ float gelu_exact(float v) {
    return 0.5f * v * (1.0f + erff(v * 0.70710678118654752f));
}

// GEMM1: h = gelu(A[token,:H] @ W1[H,F] + b1)  ->  g_h[row,:F]
__global__ void __launch_bounds__(256, 2)
gemm1_kernel(const float* __restrict__ x,
             const float* __restrict__ sw1, const float* __restrict__ sb1,
             const float* __restrict__ ew1, const float* __restrict__ eb1) {
    int rowStart = blockIdx.y * BM;
    int tid = threadIdx.x;
    __shared__ int stok[BM];
    __shared__ float As[BK][BM + 1];
    __shared__ float Bs[BK][BN];

    const float* W;
    const float* bias;
    if (rowStart < NS * T) {
        int slot = rowStart / T;
        W = sw1 + (size_t)slot * H * F;
        bias = sb1 + slot * F;
        if (tid < BM) stok[tid] = (rowStart % T) + tid;
    } else {
        int e = (rowStart - NS * T) / T;
        int l0 = (rowStart - NS * T) % T;
        int cnt = g_counts[e];
        if (l0 >= cnt) return;
        W = ew1 + (size_t)e * H * F;
        bias = eb1 + e * F;
        if (tid < BM) stok[tid] = (l0 + tid < cnt) ? g_perm[e * T + l0 + tid] : -1;
    }
    __syncthreads();

    int n0 = blockIdx.x * BN;
    int ty = tid / 16, tx = tid % 16;
    float acc[4][4];
#pragma unroll
    for (int i = 0; i < 4; i++)
#pragma unroll
        for (int j = 0; j < 4; j++) acc[i][j] = 0.0f;

    int ar = tid / 8;          // 0..31 (A row, two passes)
    int ak = (tid % 8) * 4;    // k offset, float4
    int br = tid / 16;         // 0..15 (B k-row, two passes)
    int bn = (tid % 16) * 4;   // n offset, float4

    for (int k0 = 0; k0 < H; k0 += BK) {
#pragma unroll
        for (int p = 0; p < 2; p++) {
            int r = ar + p * 32;
            int tok = stok[r];
            float4 v = make_float4(0.f, 0.f, 0.f, 0.f);
            if (tok >= 0) v = *(const float4*)(x + (size_t)tok * H + k0 + ak);
            As[ak + 0][r] = v.x; As[ak + 1][r] = v.y;
            As[ak + 2][r] = v.z; As[ak + 3][r] = v.w;
        }
#pragma unroll
        for (int p = 0; p < 2; p++) {
            int kk = br + p * 16;
            *(float4*)&Bs[kk][bn] = *(const float4*)(W + (size_t)(k0 + kk) * F + n0 + bn);
        }
        __syncthreads();
#pragma unroll
        for (int kk = 0; kk < BK; kk++) {
            float a[4];
#pragma unroll
            for (int i = 0; i < 4; i++) a[i] = As[kk][ty * 4 + i];
            float4 b = *(const float4*)&Bs[kk][tx * 4];
#pragma unroll
            for (int i = 0; i < 4; i++) {
                acc[i][0] += a[i] * b.x; acc[i][1] += a[i] * b.y;
                acc[i][2] += a[i] * b.z; acc[i][3] += a[i] * b.w;
            }
        }
        __syncthreads();
    }

#pragma unroll
    for (int i = 0; i < 4; i++) {
        int r = ty * 4 + i;
        if (stok[r] < 0) continue;
        size_t base = (size_t)(rowStart + r) * F + n0 + tx * 4;
#pragma unroll
        for (int j = 0; j < 4; j++) {
            float v = acc[i][j] + bias[n0 + tx * 4 + j];
            g_h[base + j] = gelu_exact(v);
        }
    }
}

// GEMM2: out[token,:H] += g_h[row,:F] @ W2[F,H] + b2
__global__ void __launch_bounds__(256, 2)
gemm2_kernel(const float* __restrict__ sw2, const float* __restrict__ sb2,
             const float* __restrict__ ew2, const float* __restrict__ eb2,
             float* __restrict__ out) {
    int rowStart = blockIdx.y * BM;
    int tid = threadIdx.x;
    __shared__ int stok[BM];
    __shared__ float As[BK][BM + 1];
    __shared__ float Bs[BK][BN];

    const float* W;
    const float* bias;
    if (rowStart < NS * T) {
        int slot = rowStart / T;
        W = sw2 + (size_t)slot * F * H;
        bias = sb2 + slot * H;
        if (tid < BM) stok[tid] = (rowStart % T) + tid;
    } else {
        int e = (rowStart - NS * T) / T;
        int l0 = (rowStart - NS * T) % T;
        int cnt = g_counts[e];
        if (l0 >= cnt) return;
        W = ew2 + (size_t)e * F * H;
        bias = eb2 + e * H;
        if (tid < BM) stok[tid] = (l0 + tid < cnt) ? g_perm[e * T + l0 + tid] : -1;
    }
    __syncthreads();

    int n0 = blockIdx.x * BN;
    int ty = tid / 16, tx = tid % 16;
    float acc[4][4];
#pragma unroll
    for (int i = 0; i < 4; i++)
#pragma unroll
        for (int j = 0; j < 4; j++) acc[i][j] = 0.0f;

    int ar = tid / 8;
    int ak = (tid % 8) * 4;
    int br = tid / 16;
    int bn = (tid % 16) * 4;

    for (int k0 = 0; k0 < F; k0 += BK) {
#pragma unroll
        for (int p = 0; p < 2; p++) {
            int r = ar + p * 32;
            // A = g_h, contiguous in row space (invalid rows read zeros/garbage,
            // their stores are skipped below)
            float4 v = *(const float4*)(g_h + (size_t)(rowStart + r) * F + k0 + ak);
            As[ak + 0][r] = v.x; As[ak + 1][r] = v.y;
            As[ak + 2][r] = v.z; As[ak + 3][r] = v.w;
        }
#pragma unroll
        for (int p = 0; p < 2; p++) {
            int kk = br + p * 16;
            *(float4*)&Bs[kk][bn] = *(const float4*)(W + (size_t)(k0 + kk) * H + n0 + bn);
        }
        __syncthreads();
#pragma unroll
        for (int kk = 0; kk < BK; kk++) {
            float a[4];
#pragma unroll
            for (int i = 0; i < 4; i++) a[i] = As[kk][ty * 4 + i];
            float4 b = *(const float4*)&Bs[kk][tx * 4];
#pragma unroll
            for (int i = 0; i < 4; i++) {
                acc[i][0] += a[i] * b.x; acc[i][1] += a[i] * b.y;
                acc[i][2] += a[i] * b.z; acc[i][3] += a[i] * b.w;
            }
        }
        __syncthreads();
    }

#pragma unroll
    for (int i = 0; i < 4; i++) {
        int r = ty * 4 + i;
        int tok = stok[r];
        if (tok < 0) continue;
        float* dst = out + (size_t)tok * H + n0 + tx * 4;
#pragma unroll
        for (int j = 0; j < 4; j++) {
            atomicAdd(dst + j, acc[i][j] + bias[n0 + tx * 4 + j]);
        }
    }
}

// ---------------------------------------------------------------------------
extern "C" void kernel_launch(void* const* d_in, const int* in_sizes, int n_in,
                              void* d_out, int out_size) {
    const float* x   = (const float*)d_in[0];
    const float* sw1 = (const float*)d_in[1];
    const float* sb1 = (const float*)d_in[2];
    const float* sw2 = (const float*)d_in[3];
    const float* sb2 = (const float*)d_in[4];
    const float* ew1 = (const float*)d_in[5];
    const float* eb1 = (const float*)d_in[6];
    const float* ew2 = (const float*)d_in[7];
    const float* eb2 = (const float*)d_in[8];
    const float* rw  = (const float*)d_in[9];
    const float* rb  = (const float*)d_in[10];
    float* out = (float*)d_out;

    zero_kernel<<<(T * H + 255) / 256, 256>>>(out);
    router_kernel<<<T, 256>>>(x, rw, rb);

    dim3 g1(F / BN, RTOT / BM); // 32 x 640
    gemm1_kernel<<<g1, 256>>>(x, sw1, sb1, ew1, eb1);

    dim3 g2(H / BN, RTOT / BM); // 16 x 640
    gemm2_kernel<<<g2, 256>>>(sw2, sb2, ew2, eb2, out);
}

// round 14
// speedup vs baseline: 2.5602x; 2.5602x over previous
#include <cuda_runtime.h>
#include <cuda_bf16.h>
#include <cstdint>
#include <math.h>

// Problem constants (B=4, S=1024 -> T=4096 tokens)
#define T 4096
#define H 1024
#define F 2048
#define E 8
#define NS 2
#define RTOT (NS * T + E * T) /* 40960 unified rows */

// Tensor-path GEMM tiling
#define BM 128
#define BN 128
#define KTILE 64

// SMEM stage layout: A [m=128][k=64] hi/lo (16KB each), B two n64 sub-tiles,
// each [k=64][n=64] hi/lo (8KB each)
#define OFF_AH 0
#define OFF_AL 16384
#define OFF_B  32768          /* + sub*16384 (hi), +8192 (lo) */
#define STAGE_BYTES 65536
#define DYN_BYTES (2 * STAGE_BYTES + 1024) /* 132096 */

// Fallback (round-1 proven) tiling
#define FBM 64
#define FBN 64
#define FBK 32

// ---------------------------------------------------------------------------
// Scratch: SINGLE union buffer at R1's proven size (~336 MB total statics).
// Tensor path: hh = (bf16*)g_scratch [RTOT*F], hl = hh + RTOT*F.
// Fallback:    hf = (float*)g_scratch [RTOT*F].
__device__ unsigned char g_scratch[(size_t)RTOT * F * 4];
__device__ int g_perm[E * T];
__device__ int g_counts[E];

// ---------------------------------------------------------------------------
__device__ __forceinline__ uint32_t smem_u32(const void* p) {
    uint32_t a;
    asm("{ .reg .u64 t; cvta.to.shared.u64 t, %1; cvt.u32.u64 %0, t; }" : "=r"(a) : "l"(p));
    return a;
}
__device__ __forceinline__ void ldsm_x4(uint32_t addr, uint32_t (&r)[4]) {
    asm volatile("ldmatrix.sync.aligned.m8n8.x4.shared.b16 {%0,%1,%2,%3}, [%4];"
                 : "=r"(r[0]), "=r"(r[1]), "=r"(r[2]), "=r"(r[3]) : "r"(addr));
}
__device__ __forceinline__ void ldsm_x4_t(uint32_t addr, uint32_t (&r)[4]) {
    asm volatile("ldmatrix.sync.aligned.m8n8.x4.trans.shared.b16 {%0,%1,%2,%3}, [%4];"
                 : "=r"(r[0]), "=r"(r[1]), "=r"(r[2]), "=r"(r[3]) : "r"(addr));
}
__device__ __forceinline__ void mma_bf16(float (&d)[4], const uint32_t (&a)[4],
                                         uint32_t b0, uint32_t b1) {
    asm volatile(
        "mma.sync.aligned.m16n8k16.row.col.f32.bf16.bf16.f32 "
        "{%0,%1,%2,%3}, {%4,%5,%6,%7}, {%8,%9}, {%0,%1,%2,%3};"
        : "+f"(d[0]), "+f"(d[1]), "+f"(d[2]), "+f"(d[3])
        : "r"(a[0]), "r"(a[1]), "r"(a[2]), "r"(a[3]), "r"(b0), "r"(b1));
}
__device__ __forceinline__ float gelu_exact(float v) {
    return 0.5f * v * (1.0f + erff(v * 0.70710678118654752f));
}
__device__ __forceinline__ void split_bf16(float v, __nv_bfloat16& hi, __nv_bfloat16& lo) {
    hi = __float2bfloat16(v);
    lo = __float2bfloat16(v - __bfloat162float(hi));
}
__device__ __forceinline__ uint32_t pack_bf16(__nv_bfloat16 a, __nv_bfloat16 b) {
    return (uint32_t)__bfloat16_as_ushort(a) | ((uint32_t)__bfloat16_as_ushort(b) << 16);
}
// 8 fp32 -> 8 bf16 hi (uint4) + 8 bf16 lo (uint4)
__device__ __forceinline__ void cvt8(const float4& a, const float4& b,
                                     uint4& hi, uint4& lo) {
    float f[8] = {a.x, a.y, a.z, a.w, b.x, b.y, b.z, b.w};
    __nv_bfloat16 h[8], l[8];
#pragma unroll
    for (int i = 0; i < 8; i++) split_bf16(f[i], h[i], l[i]);
    hi = make_uint4(pack_bf16(h[0], h[1]), pack_bf16(h[2], h[3]),
                    pack_bf16(h[4], h[5]), pack_bf16(h[6], h[7]));
    lo = make_uint4(pack_bf16(l[0], l[1]), pack_bf16(l[2], l[3]),
                    pack_bf16(l[4], l[5]), pack_bf16(l[6], l[7]));
}

// Warp-tile compute on one K-stage (64 bf16): A [m][k] non-trans, B [k][n] trans.
__device__ __forceinline__ void compute_stage(uint32_t sbase, int wm, int wn, int lane,
                                              float (&acc)[2][8][4]) {
    const uint32_t sa_h = sbase + OFF_AH, sa_l = sbase + OFF_AL;
    const uint32_t sb_h = sbase + OFF_B + wn * 16384, sb_l = sb_h + 8192;
    int lrow = lane & 15;
    int lsel = lane >> 4;
#pragma unroll
    for (int c = 0; c < 4; c++) {
        int unit = c * 2 + lsel;
        uint32_t ah[2][4], al[2][4], bt[4][4], blt[4][4];
#pragma unroll
        for (int mf = 0; mf < 2; mf++) {
            int row = wm * 32 + mf * 16 + lrow;
            ldsm_x4(sa_h + row * 128 + ((unit ^ (row & 7)) << 4), ah[mf]);
        }
        // B: rows are k (within 0..63), cols n. Lanes 0-7:(k c*16+0..7,u 2nf),
        // 8-15:(k+8,u 2nf), 16-23:(k0-7,u 2nf+1), 24-31:(k+8,u 2nf+1).
        int brow0 = c * 16 + (lane & 15);
        int buadd = lane >> 4;
#pragma unroll
        for (int nf = 0; nf < 4; nf++) {
            int bu = 2 * nf + buadd;
            ldsm_x4_t(sb_h + brow0 * 128 + ((bu ^ (brow0 & 7)) << 4), bt[nf]);
        }
        // hi * hi
#pragma unroll
        for (int mf = 0; mf < 2; mf++)
#pragma unroll
            for (int j = 0; j < 8; j++)
                mma_bf16(acc[mf][j], ah[mf], bt[j >> 1][(j & 1) * 2], bt[j >> 1][(j & 1) * 2 + 1]);
        // lo(A) * hi(B)
#pragma unroll
        for (int mf = 0; mf < 2; mf++) {
            int row = wm * 32 + mf * 16 + lrow;
            ldsm_x4(sa_l + row * 128 + ((unit ^ (row & 7)) << 4), al[mf]);
        }
#pragma unroll
        for (int mf = 0; mf < 2; mf++)
#pragma unroll
            for (int j = 0; j < 8; j++)
                mma_bf16(acc[mf][j], al[mf], bt[j >> 1][(j & 1) * 2], bt[j >> 1][(j & 1) * 2 + 1]);
        // hi(A) * lo(B)
#pragma unroll
        for (int nf = 0; nf < 4; nf++) {
            int bu = 2 * nf + buadd;
            ldsm_x4_t(sb_l + brow0 * 128 + ((bu ^ (brow0 & 7)) << 4), blt[nf]);
        }
#pragma unroll
        for (int mf = 0; mf < 2; mf++)
#pragma unroll
            for (int j = 0; j < 8; j++)
                mma_bf16(acc[mf][j], ah[mf], blt[j >> 1][(j & 1) * 2], blt[j >> 1][(j & 1) * 2 + 1]);
    }
}

// ---------------------------------------------------------------------------
__global__ void zero_kernel(float* __restrict__ out) {
    int i = blockIdx.x * blockDim.x + threadIdx.x;
    if (i < T * H) out[i] = 0.0f;
    if (i < E) g_counts[i] = 0;
}

__global__ void router_kernel(const float* __restrict__ x,
                              const float* __restrict__ rw,
                              const float* __restrict__ rb) {
    int t = blockIdx.x;
    const float* xt = x + (size_t)t * H;
    float acc[E];
#pragma unroll
    for (int e = 0; e < E; e++) acc[e] = 0.0f;
    for (int h = threadIdx.x; h < H; h += blockDim.x) {
        float xv = xt[h];
#pragma unroll
        for (int e = 0; e < E; e++) acc[e] += xv * rw[h * E + e];
    }
    __shared__ float red[256];
    __shared__ float logits[E];
#pragma unroll
    for (int e = 0; e < E; e++) {
        red[threadIdx.x] = acc[e];
        __syncthreads();
        for (int s = 128; s > 0; s >>= 1) {
            if (threadIdx.x < s) red[threadIdx.x] += red[threadIdx.x + s];
            __syncthreads();
        }
        if (threadIdx.x == 0) logits[e] = red[0] + rb[e];
        __syncthreads();
    }
    if (threadIdx.x == 0) {
        int e0 = 0;
        float v0 = logits[0];
#pragma unroll
        for (int e = 1; e < E; e++)
            if (logits[e] > v0) { v0 = logits[e]; e0 = e; }
        int e1 = -1;
        float v1 = -3.0e38f;
#pragma unroll
        for (int e = 0; e < E; e++)
            if (e != e0 && logits[e] > v1) { v1 = logits[e]; e1 = e; }
        int p0 = atomicAdd(&g_counts[e0], 1);
        g_perm[e0 * T + p0] = t;
        int p1 = atomicAdd(&g_counts[e1], 1);
        g_perm[e1 * T + p1] = t;
    }
}

// ---------------------------------------------------------------------------
// Tensor GEMM1: fp32 inputs split to bf16 hi/lo during staging.
__global__ void __launch_bounds__(256, 1)
gemm1_kernel(const float* __restrict__ x,
             const float* __restrict__ sw1, const float* __restrict__ sb1,
             const float* __restrict__ ew1, const float* __restrict__ eb1) {
    int rowStart = blockIdx.y * BM;
    int tid = threadIdx.x, wid = tid >> 5, lane = tid & 31;
    int wm = wid & 3, wn = wid >> 2;

    __shared__ int stok[BM];
    extern __shared__ char dynraw[];

    const float* W;
    const float* bias;
    if (rowStart < NS * T) {
        int slot = rowStart / T;
        W = sw1 + (size_t)slot * H * F;
        bias = sb1 + slot * F;
        if (tid < BM) stok[tid] = (rowStart % T) + tid;
    } else {
        int e = (rowStart - NS * T) / T;
        int l0 = (rowStart - NS * T) % T;
        int cnt = g_counts[e];
        if (l0 >= cnt) return;
        W = ew1 + (size_t)e * H * F;
        bias = eb1 + e * F;
        if (tid < BM) stok[tid] = (l0 + tid < cnt) ? g_perm[e * T + l0 + tid] : -1;
    }
    __syncthreads();

    char* dyn = (char*)(((uintptr_t)dynraw + 1023) & ~(uintptr_t)1023);
    uint32_t dyn32 = smem_u32(dyn);
    int n0 = blockIdx.x * BN;
    __nv_bfloat16* hh = (__nv_bfloat16*)g_scratch;
    __nv_bfloat16* hl = hh + (size_t)RTOT * F;

    const int NK = H / KTILE; // 16

    float4 la[4][2], lb[4][2];
    auto ldregs = [&](int it) {
        int k0 = it * KTILE;
#pragma unroll
        for (int q = 0; q < 4; q++) { // A: 128 rows x 8 groups of 8 floats
            int g = q * 256 + tid;
            int row = g >> 3, grp = g & 7;
            int tok = stok[row];
            const float* src = x + (size_t)(tok >= 0 ? tok : 0) * H + k0 + grp * 8;
            la[q][0] = *(const float4*)src;
            la[q][1] = *(const float4*)(src + 4);
        }
#pragma unroll
        for (int q = 0; q < 4; q++) { // B: 64 k-rows x 16 groups of 8 floats
            int g = q * 256 + tid;
            int row = g >> 4, grp = g & 15;
            const float* src = W + (size_t)(k0 + row) * F + n0 + grp * 8;
            lb[q][0] = *(const float4*)src;
            lb[q][1] = *(const float4*)(src + 4);
        }
    };
    auto cvst = [&](int s) {
        char* st = dyn + s * STAGE_BYTES;
#pragma unroll
        for (int q = 0; q < 4; q++) {
            int g = q * 256 + tid;
            int row = g >> 3, grp = g & 7;
            uint32_t d = row * 128 + ((grp ^ (row & 7)) << 4);
            uint4 hi, lo;
            cvt8(la[q][0], la[q][1], hi, lo);
            *(uint4*)(st + OFF_AH + d) = hi;
            *(uint4*)(st + OFF_AL + d) = lo;
        }
#pragma unroll
        for (int q = 0; q < 4; q++) {
            int g = q * 256 + tid;
            int row = g >> 4, grp = g & 15;
            int sub = grp >> 3, u = grp & 7;
            uint32_t d = sub * 16384 + row * 128 + ((u ^ (row & 7)) << 4);
            uint4 hi, lo;
            cvt8(lb[q][0], lb[q][1], hi, lo);
            *(uint4*)(st + OFF_B + d) = hi;
            *(uint4*)(st + OFF_B + 8192 + d) = lo;
        }
    };

    float acc[2][8][4];
#pragma unroll
    for (int a = 0; a < 2; a++)
#pragma unroll
        for (int b = 0; b < 8; b++)
#pragma unroll
            for (int c = 0; c < 4; c++) acc[a][b][c] = 0.0f;

    ldregs(0);
    cvst(0);
    ldregs(1);
    __syncthreads();

    for (int it = 0; it < NK; it++) {
        compute_stage(dyn32 + (it & 1) * STAGE_BYTES, wm, wn, lane, acc);
        if (it + 1 < NK) cvst((it + 1) & 1);
        __syncthreads();
        if (it + 2 < NK) ldregs(it + 2);
    }

    // Epilogue: bias + exact gelu + split -> hh/hl
    int lr = lane >> 2;
    int lc = (lane & 3) * 2;
#pragma unroll
    for (int mf = 0; mf < 2; mf++) {
#pragma unroll
        for (int half = 0; half < 2; half++) {
            int m = wm * 32 + mf * 16 + lr + half * 8;
            if (stok[m] < 0) continue;
            size_t rowbase = (size_t)(rowStart + m) * F;
#pragma unroll
            for (int j = 0; j < 8; j++) {
                int col = n0 + wn * 64 + j * 8 + lc;
                float v0 = gelu_exact(acc[mf][j][half * 2 + 0] + __ldg(&bias[col]));
                float v1 = gelu_exact(acc[mf][j][half * 2 + 1] + __ldg(&bias[col + 1]));
                __nv_bfloat16 h0, l0, h1, l1;
                split_bf16(v0, h0, l0);
                split_bf16(v1, h1, l1);
                *(uint32_t*)(hh + rowbase + col) = pack_bf16(h0, h1);
                *(uint32_t*)(hl + rowbase + col) = pack_bf16(l0, l1);
            }
        }
    }
}

// Tensor GEMM2: A from bf16 scratch, B = w2 fp32 split during staging.
__global__ void __launch_bounds__(256, 1)
gemm2_kernel(const float* __restrict__ sw2, const float* __restrict__ sb2,
             const float* __restrict__ ew2, const float* __restrict__ eb2,
             float* __restrict__ out) {
    int rowStart = blockIdx.y * BM;
    int tid = threadIdx.x, wid = tid >> 5, lane = tid & 31;
    int wm = wid & 3, wn = wid >> 2;

    __shared__ int stok[BM];
    extern __shared__ char dynraw[];

    const float* W;
    const float* bias;
    if (rowStart < NS * T) {
        int slot = rowStart / T;
        W = sw2 + (size_t)slot * F * H;
        bias = sb2 + slot * H;
        if (tid < BM) stok[tid] = (rowStart % T) + tid;
    } else {
        int e = (rowStart - NS * T) / T;
        int l0 = (rowStart - NS * T) % T;
        int cnt = g_counts[e];
        if (l0 >= cnt) return;
        W = ew2 + (size_t)e * F * H;
        bias = eb2 + e * H;
        if (tid < BM) stok[tid] = (l0 + tid < cnt) ? g_perm[e * T + l0 + tid] : -1;
    }
    __syncthreads();

    char* dyn = (char*)(((uintptr_t)dynraw + 1023) & ~(uintptr_t)1023);
    uint32_t dyn32 = smem_u32(dyn);
    int n0 = blockIdx.x * BN;
    const __nv_bfloat16* hh = (const __nv_bfloat16*)g_scratch;
    const __nv_bfloat16* hl = hh + (size_t)RTOT * F;

    const int NK = F / KTILE; // 32

    uint4 lah[4], lal[4];
    float4 lb[4][2];
    auto ldregs = [&](int it) {
        int k0 = it * KTILE;
#pragma unroll
        for (int q = 0; q < 4; q++) {
            int g = q * 256 + tid;
            int row = g >> 3, grp = g & 7;
            size_t o = (size_t)(rowStart + row) * F + k0 + grp * 8;
            lah[q] = *(const uint4*)(hh + o);
            lal[q] = *(const uint4*)(hl + o);
        }
#pragma unroll
        for (int q = 0; q < 4; q++) {
            int g = q * 256 + tid;
            int row = g >> 4, grp = g & 15;
            const float* src = W + (size_t)(k0 + row) * H + n0 + grp * 8;
            lb[q][0] = *(const float4*)src;
            lb[q][1] = *(const float4*)(src + 4);
        }
    };
    auto cvst = [&](int s) {
        char* st = dyn + s * STAGE_BYTES;
#pragma unroll
        for (int q = 0; q < 4; q++) {
            int g = q * 256 + tid;
            int row = g >> 3, grp = g & 7;
            uint32_t d = row * 128 + ((grp ^ (row & 7)) << 4);
            *(uint4*)(st + OFF_AH + d) = lah[q];
            *(uint4*)(st + OFF_AL + d) = lal[q];
        }
#pragma unroll
        for (int q = 0; q < 4; q++) {
            int g = q * 256 + tid;
            int row = g >> 4, grp = g & 15;
            int sub = grp >> 3, u = grp & 7;
            uint32_t d = sub * 16384 + row * 128 + ((u ^ (row & 7)) << 4);
            uint4 hi, lo;
            cvt8(lb[q][0], lb[q][1], hi, lo);
            *(uint4*)(st + OFF_B + d) = hi;
            *(uint4*)(st + OFF_B + 8192 + d) = lo;
        }
    };

    float acc[2][8][4];
#pragma unroll
    for (int a = 0; a < 2; a++)
#pragma unroll
        for (int b = 0; b < 8; b++)
#pragma unroll
            for (int c = 0; c < 4; c++) acc[a][b][c] = 0.0f;

    ldregs(0);
    cvst(0);
    ldregs(1);
    __syncthreads();

    for (int it = 0; it < NK; it++) {
        compute_stage(dyn32 + (it & 1) * STAGE_BYTES, wm, wn, lane, acc);
        if (it + 1 < NK) cvst((it + 1) & 1);
        __syncthreads();
        if (it + 2 < NK) ldregs(it + 2);
    }

    int lr = lane >> 2;
    int lc = (lane & 3) * 2;
#pragma unroll
    for (int mf = 0; mf < 2; mf++) {
#pragma unroll
        for (int half = 0; half < 2; half++) {
            int m = wm * 32 + mf * 16 + lr + half * 8;
            int tok = stok[m];
            if (tok < 0) continue;
            float* dst = out + (size_t)tok * H;
#pragma unroll
            for (int j = 0; j < 8; j++) {
                int col = n0 + wn * 64 + j * 8 + lc;
                atomicAdd(dst + col, acc[mf][j][half * 2 + 0] + __ldg(&bias[col]));
                atomicAdd(dst + col + 1, acc[mf][j][half * 2 + 1] + __ldg(&bias[col + 1]));
            }
        }
    }
}

// ---------------------------------------------------------------------------
// Fallback SIMT kernels (round-1 design; hf aliases g_scratch)
__global__ void __launch_bounds__(256, 2)
fb_gemm1_kernel(const float* __restrict__ x,
                const float* __restrict__ sw1, const float* __restrict__ sb1,
                const float* __restrict__ ew1, const float* __restrict__ eb1) {
    float* hf = (float*)g_scratch;
    int rowStart = blockIdx.y * FBM;
    int tid = threadIdx.x;
    __shared__ int stok[FBM];
    __shared__ float As[FBK][FBM + 1];
    __shared__ float Bs[FBK][FBN];

    const float* W;
    const float* bias;
    if (rowStart < NS * T) {
        int slot = rowStart / T;
        W = sw1 + (size_t)slot * H * F;
        bias = sb1 + slot * F;
        if (tid < FBM) stok[tid] = (rowStart % T) + tid;
    } else {
        int e = (rowStart - NS * T) / T;
        int l0 = (rowStart - NS * T) % T;
        int cnt = g_counts[e];
        if (l0 >= cnt) return;
        W = ew1 + (size_t)e * H * F;
        bias = eb1 + e * F;
        if (tid < FBM) stok[tid] = (l0 + tid < cnt) ? g_perm[e * T + l0 + tid] : -1;
    }
    __syncthreads();

    int n0 = blockIdx.x * FBN;
    int ty = tid / 16, tx = tid % 16;
    float acc[4][4];
#pragma unroll
    for (int i = 0; i < 4; i++)
#pragma unroll
        for (int j = 0; j < 4; j++) acc[i][j] = 0.0f;

    int ar = tid / 8, ak = (tid % 8) * 4;
    int br = tid / 16, bn = (tid % 16) * 4;

    for (int k0 = 0; k0 < H; k0 += FBK) {
#pragma unroll
        for (int p = 0; p < 2; p++) {
            int r = ar + p * 32;
            int tok = stok[r];
            float4 v = make_float4(0.f, 0.f, 0.f, 0.f);
            if (tok >= 0) v = *(const float4*)(x + (size_t)tok * H + k0 + ak);
            As[ak + 0][r] = v.x; As[ak + 1][r] = v.y;
            As[ak + 2][r] = v.z; As[ak + 3][r] = v.w;
        }
#pragma unroll
        for (int p = 0; p < 2; p++) {
            int kk = br + p * 16;
            *(float4*)&Bs[kk][bn] = *(const float4*)(W + (size_t)(k0 + kk) * F + n0 + bn);
        }
        __syncthreads();
#pragma unroll
        for (int kk = 0; kk < FBK; kk++) {
            float a[4];
#pragma unroll
            for (int i = 0; i < 4; i++) a[i] = As[kk][ty * 4 + i];
            float4 b = *(const float4*)&Bs[kk][tx * 4];
#pragma unroll
            for (int i = 0; i < 4; i++) {
                acc[i][0] += a[i] * b.x; acc[i][1] += a[i] * b.y;
                acc[i][2] += a[i] * b.z; acc[i][3] += a[i] * b.w;
            }
        }
        __syncthreads();
    }

#pragma unroll
    for (int i = 0; i < 4; i++) {
        int r = ty * 4 + i;
        if (stok[r] < 0) continue;
        size_t base = (size_t)(rowStart + r) * F + n0 + tx * 4;
#pragma unroll
        for (int j = 0; j < 4; j++) {
            float v = acc[i][j] + bias[n0 + tx * 4 + j];
            hf[base + j] = gelu_exact(v);
        }
    }
}

__global__ void __launch_bounds__(256, 2)
fb_gemm2_kernel(const float* __restrict__ sw2, const float* __restrict__ sb2,
                const float* __restrict__ ew2, const float* __restrict__ eb2,
                float* __restrict__ out) {
    const float* hf = (const float*)g_scratch;
    int rowStart = blockIdx.y * FBM;
    int tid = threadIdx.x;
    __shared__ int stok[FBM];
    __shared__ float As[FBK][FBM + 1];
    __shared__ float Bs[FBK][FBN];

    const float* W;
    const float* bias;
    if (rowStart < NS * T) {
        int slot = rowStart / T;
        W = sw2 + (size_t)slot * F * H;
        bias = sb2 + slot * H;
        if (tid < FBM) stok[tid] = (rowStart % T) + tid;
    } else {
        int e = (rowStart - NS * T) / T;
        int l0 = (rowStart - NS * T) % T;
        int cnt = g_counts[e];
        if (l0 >= cnt) return;
        W = ew2 + (size_t)e * F * H;
        bias = eb2 + e * H;
        if (tid < FBM) stok[tid] = (l0 + tid < cnt) ? g_perm[e * T + l0 + tid] : -1;
    }
    __syncthreads();

    int n0 = blockIdx.x * FBN;
    int ty = tid / 16, tx = tid % 16;
    float acc[4][4];
#pragma unroll
    for (int i = 0; i < 4; i++)
#pragma unroll
        for (int j = 0; j < 4; j++) acc[i][j] = 0.0f;

    int ar = tid / 8, ak = (tid % 8) * 4;
    int br = tid / 16, bn = (tid % 16) * 4;

    for (int k0 = 0; k0 < F; k0 += FBK) {
#pragma unroll
        for (int p = 0; p < 2; p++) {
            int r = ar + p * 32;
            float4 v = *(const float4*)(hf + (size_t)(rowStart + r) * F + k0 + ak);
            As[ak + 0][r] = v.x; As[ak + 1][r] = v.y;
            As[ak + 2][r] = v.z; As[ak + 3][r] = v.w;
        }
#pragma unroll
        for (int p = 0; p < 2; p++) {
            int kk = br + p * 16;
            *(float4*)&Bs[kk][bn] = *(const float4*)(W + (size_t)(k0 + kk) * H + n0 + bn);
        }
        __syncthreads();
#pragma unroll
        for (int kk = 0; kk < FBK; kk++) {
            float a[4];
#pragma unroll
            for (int i = 0; i < 4; i++) a[i] = As[kk][ty * 4 + i];
            float4 b = *(const float4*)&Bs[kk][tx * 4];
#pragma unroll
            for (int i = 0; i < 4; i++) {
                acc[i][0] += a[i] * b.x; acc[i][1] += a[i] * b.y;
                acc[i][2] += a[i] * b.z; acc[i][3] += a[i] * b.w;
            }
        }
        __syncthreads();
    }

#pragma unroll
    for (int i = 0; i < 4; i++) {
        int r = ty * 4 + i;
        int tok = stok[r];
        if (tok < 0) continue;
        float* dst = out + (size_t)tok * H + n0 + tx * 4;
#pragma unroll
        for (int j = 0; j < 4; j++) {
            atomicAdd(dst + j, acc[i][j] + bias[n0 + tx * 4 + j]);
        }
    }
}

// ---------------------------------------------------------------------------
static void launch_fallback(const float* x,
                            const float* sw1, const float* sb1,
                            const float* sw2, const float* sb2,
                            const float* ew1, const float* eb1,
                            const float* ew2, const float* eb2,
                            float* out) {
    dim3 g1(F / FBN, RTOT / FBM);
    fb_gemm1_kernel<<<g1, 256>>>(x, sw1, sb1, ew1, eb1);
    dim3 g2(H / FBN, RTOT / FBM);
    fb_gemm2_kernel<<<g2, 256>>>(sw2, sb2, ew2, eb2, out);
}

extern "C" void kernel_launch(void* const* d_in, const int* in_sizes, int n_in,
                              void* d_out, int out_size) {
    const float* x   = (const float*)d_in[0];
    const float* sw1 = (const float*)d_in[1];
    const float* sb1 = (const float*)d_in[2];
    const float* sw2 = (const float*)d_in[3];
    const float* sb2 = (const float*)d_in[4];
    const float* ew1 = (const float*)d_in[5];
    const float* eb1 = (const float*)d_in[6];
    const float* ew2 = (const float*)d_in[7];
    const float* eb2 = (const float*)d_in[8];
    const float* rw  = (const float*)d_in[9];
    const float* rb  = (const float*)d_in[10];
    float* out = (float*)d_out;

    bool tensor_ok = true;
    if (cudaFuncSetAttribute(gemm1_kernel, cudaFuncAttributeMaxDynamicSharedMemorySize,
                             DYN_BYTES) != cudaSuccess) tensor_ok = false;
    if (cudaFuncSetAttribute(gemm2_kernel, cudaFuncAttributeMaxDynamicSharedMemorySize,
                             DYN_BYTES) != cudaSuccess) tensor_ok = false;

    zero_kernel<<<(T * H + 255) / 256, 256>>>(out);
    router_kernel<<<T, 256>>>(x, rw, rb);

    if (tensor_ok) {
        (void)cudaGetLastError(); // clear before the tensor chain
        dim3 g1(F / BN, RTOT / BM); // 16 x 320
        gemm1_kernel<<<g1, 256, DYN_BYTES>>>(x, sw1, sb1, ew1, eb1);
        dim3 g2(H / BN, RTOT / BM); // 8 x 320
        gemm2_kernel<<<g2, 256, DYN_BYTES>>>(sw2, sb2, ew2, eb2, out);
        if (cudaGetLastError() != cudaSuccess) {
            // Launch-config failure: tensor gemms contributed nothing real;
            // recompute with the proven SIMT path (hf aliases the same scratch).
            launch_fallback(x, sw1, sb1, sw2, sb2, ew1, eb1, ew2, eb2, out);
        }
    } else {
        launch_fallback(x, sw1, sb1, sw2, sb2, ew1, eb1, ew2, eb2, out);
    }
}

// round 16
// speedup vs baseline: 2.6061x; 1.0179x over previous
#include <cuda_runtime.h>
#include <cuda_bf16.h>
#include <cstdint>
#include <math.h>

// Problem constants (B=4, S=1024 -> T=4096 tokens)
#define T 4096
#define H 1024
#define F 2048
#define E 8
#define NS 2
#define RTOT (NS * T + E * T) /* 40960 unified rows */

// Tensor-path GEMM tiling
#define BM 128
#define BN 128
#define KTILE 64
#define THREADS 512

// SMEM stage layout: A [m=128][k=64] hi/lo (16KB each), B two n64 sub-tiles,
// each [k=64][n=64] hi/lo (8KB each)
#define OFF_AH 0
#define OFF_AL 16384
#define OFF_B  32768          /* + sub*16384 (hi), +8192 (lo) */
#define STAGE_BYTES 65536
#define DYN_BYTES (2 * STAGE_BYTES + 1024) /* 132096 */

// Fallback (round-1 proven) tiling
#define FBM 64
#define FBN 64
#define FBK 32

// ---------------------------------------------------------------------------
// Scratch: SINGLE union buffer at R1's proven size (~336 MB total statics).
// Tensor path: hh = (bf16*)g_scratch [RTOT*F], hl = hh + RTOT*F.
// Fallback:    hf = (float*)g_scratch [RTOT*F].
__device__ unsigned char g_scratch[(size_t)RTOT * F * 4];
__device__ int g_perm[E * T];
__device__ int g_counts[E];

// ---------------------------------------------------------------------------
__device__ __forceinline__ uint32_t smem_u32(const void* p) {
    uint32_t a;
    asm("{ .reg .u64 t; cvta.to.shared.u64 t, %1; cvt.u32.u64 %0, t; }" : "=r"(a) : "l"(p));
    return a;
}
__device__ __forceinline__ void ldsm_x4(uint32_t addr, uint32_t (&r)[4]) {
    asm volatile("ldmatrix.sync.aligned.m8n8.x4.shared.b16 {%0,%1,%2,%3}, [%4];"
                 : "=r"(r[0]), "=r"(r[1]), "=r"(r[2]), "=r"(r[3]) : "r"(addr));
}
__device__ __forceinline__ void ldsm_x4_t(uint32_t addr, uint32_t (&r)[4]) {
    asm volatile("ldmatrix.sync.aligned.m8n8.x4.trans.shared.b16 {%0,%1,%2,%3}, [%4];"
                 : "=r"(r[0]), "=r"(r[1]), "=r"(r[2]), "=r"(r[3]) : "r"(addr));
}
__device__ __forceinline__ void mma_bf16(float (&d)[4], const uint32_t (&a)[4],
                                         uint32_t b0, uint32_t b1) {
    asm volatile(
        "mma.sync.aligned.m16n8k16.row.col.f32.bf16.bf16.f32 "
        "{%0,%1,%2,%3}, {%4,%5,%6,%7}, {%8,%9}, {%0,%1,%2,%3};"
        : "+f"(d[0]), "+f"(d[1]), "+f"(d[2]), "+f"(d[3])
        : "r"(a[0]), "r"(a[1]), "r"(a[2]), "r"(a[3]), "r"(b0), "r"(b1));
}
__device__ __forceinline__ float gelu_exact(float v) {
    return 0.5f * v * (1.0f + erff(v * 0.70710678118654752f));
}
__device__ __forceinline__ void split_bf16(float v, __nv_bfloat16& hi, __nv_bfloat16& lo) {
    hi = __float2bfloat16(v);
    lo = __float2bfloat16(v - __bfloat162float(hi));
}
__device__ __forceinline__ uint32_t pack_bf16(__nv_bfloat16 a, __nv_bfloat16 b) {
    return (uint32_t)__bfloat16_as_ushort(a) | ((uint32_t)__bfloat16_as_ushort(b) << 16);
}
// 8 fp32 -> 8 bf16 hi (uint4) + 8 bf16 lo (uint4)
__device__ __forceinline__ void cvt8(const float4& a, const float4& b,
                                     uint4& hi, uint4& lo) {
    float f[8] = {a.x, a.y, a.z, a.w, b.x, b.y, b.z, b.w};
    __nv_bfloat16 h[8], l[8];
#pragma unroll
    for (int i = 0; i < 8; i++) split_bf16(f[i], h[i], l[i]);
    hi = make_uint4(pack_bf16(h[0], h[1]), pack_bf16(h[2], h[3]),
                    pack_bf16(h[4], h[5]), pack_bf16(h[6], h[7]));
    lo = make_uint4(pack_bf16(l[0], l[1]), pack_bf16(l[2], l[3]),
                    pack_bf16(l[4], l[5]), pack_bf16(l[6], l[7]));
}

// Warp-tile compute on one K-stage (64 bf16). 16 warps: 4m x 4n, 32x32 per warp.
// A [m][k] non-trans, B [k][n] via ldmatrix.trans. (Proven map from R14.)
__device__ __forceinline__ void compute_stage(uint32_t sbase, int wm, int wn, int lane,
                                              float (&acc)[2][4][4]) {
    const uint32_t sa_h = sbase + OFF_AH, sa_l = sbase + OFF_AL;
    const uint32_t sb_h = sbase + OFF_B + (wn >> 1) * 16384, sb_l = sb_h + 8192;
    int lrow = lane & 15;
    int lsel = lane >> 4;
    int ubase = (wn & 1) * 4;  // n32 slice within the n64 sub-tile
#pragma unroll
    for (int c = 0; c < 4; c++) {
        int unit = c * 2 + lsel;
        uint32_t ah[2][4], al[2][4], bt[2][4], blt[2][4];
#pragma unroll
        for (int mf = 0; mf < 2; mf++) {
            int row = wm * 32 + mf * 16 + lrow;
            ldsm_x4(sa_h + row * 128 + ((unit ^ (row & 7)) << 4), ah[mf]);
        }
        int brow0 = c * 16 + lrow;
#pragma unroll
        for (int nf = 0; nf < 2; nf++) {
            int bu = ubase + 2 * nf + lsel;
            ldsm_x4_t(sb_h + brow0 * 128 + ((bu ^ (brow0 & 7)) << 4), bt[nf]);
        }
        // hi * hi
#pragma unroll
        for (int mf = 0; mf < 2; mf++)
#pragma unroll
            for (int j = 0; j < 4; j++)
                mma_bf16(acc[mf][j], ah[mf], bt[j >> 1][(j & 1) * 2], bt[j >> 1][(j & 1) * 2 + 1]);
        // lo(A) * hi(B)
#pragma unroll
        for (int mf = 0; mf < 2; mf++) {
            int row = wm * 32 + mf * 16 + lrow;
            ldsm_x4(sa_l + row * 128 + ((unit ^ (row & 7)) << 4), al[mf]);
        }
#pragma unroll
        for (int mf = 0; mf < 2; mf++)
#pragma unroll
            for (int j = 0; j < 4; j++)
                mma_bf16(acc[mf][j], al[mf], bt[j >> 1][(j & 1) * 2], bt[j >> 1][(j & 1) * 2 + 1]);
        // hi(A) * lo(B)
#pragma unroll
        for (int nf = 0; nf < 2; nf++) {
            int bu = ubase + 2 * nf + lsel;
            ldsm_x4_t(sb_l + brow0 * 128 + ((bu ^ (brow0 & 7)) << 4), blt[nf]);
        }
#pragma unroll
        for (int mf = 0; mf < 2; mf++)
#pragma unroll
            for (int j = 0; j < 4; j++)
                mma_bf16(acc[mf][j], ah[mf], blt[j >> 1][(j & 1) * 2], blt[j >> 1][(j & 1) * 2 + 1]);
    }
}

// ---------------------------------------------------------------------------
__global__ void zero_kernel(float* __restrict__ out) {
    int i = blockIdx.x * blockDim.x + threadIdx.x;
    if (i < T * H) out[i] = 0.0f;
    if (i < E) g_counts[i] = 0;
}

__global__ void router_kernel(const float* __restrict__ x,
                              const float* __restrict__ rw,
                              const float* __restrict__ rb) {
    int t = blockIdx.x;
    const float* xt = x + (size_t)t * H;
    float acc[E];
#pragma unroll
    for (int e = 0; e < E; e++) acc[e] = 0.0f;
    for (int h = threadIdx.x; h < H; h += blockDim.x) {
        float xv = xt[h];
#pragma unroll
        for (int e = 0; e < E; e++) acc[e] += xv * rw[h * E + e];
    }
    __shared__ float red[256];
    __shared__ float logits[E];
#pragma unroll
    for (int e = 0; e < E; e++) {
        red[threadIdx.x] = acc[e];
        __syncthreads();
        for (int s = 128; s > 0; s >>= 1) {
            if (threadIdx.x < s) red[threadIdx.x] += red[threadIdx.x + s];
            __syncthreads();
        }
        if (threadIdx.x == 0) logits[e] = red[0] + rb[e];
        __syncthreads();
    }
    if (threadIdx.x == 0) {
        int e0 = 0;
        float v0 = logits[0];
#pragma unroll
        for (int e = 1; e < E; e++)
            if (logits[e] > v0) { v0 = logits[e]; e0 = e; }
        int e1 = -1;
        float v1 = -3.0e38f;
#pragma unroll
        for (int e = 0; e < E; e++)
            if (e != e0 && logits[e] > v1) { v1 = logits[e]; e1 = e; }
        int p0 = atomicAdd(&g_counts[e0], 1);
        g_perm[e0 * T + p0] = t;
        int p1 = atomicAdd(&g_counts[e1], 1);
        g_perm[e1 * T + p1] = t;
    }
}

// ---------------------------------------------------------------------------
// Tensor GEMM1: fp32 inputs split to bf16 hi/lo during staging. 512 threads.
__global__ void __launch_bounds__(THREADS, 1)
gemm1_kernel(const float* __restrict__ x,
             const float* __restrict__ sw1, const float* __restrict__ sb1,
             const float* __restrict__ ew1, const float* __restrict__ eb1) {
    int rowStart = blockIdx.y * BM;
    int tid = threadIdx.x, wid = tid >> 5, lane = tid & 31;
    int wm = wid & 3, wn = wid >> 2;

    __shared__ int stok[BM];
    extern __shared__ char dynraw[];

    const float* W;
    const float* bias;
    if (rowStart < NS * T) {
        int slot = rowStart / T;
        W = sw1 + (size_t)slot * H * F;
        bias = sb1 + slot * F;
        if (tid < BM) stok[tid] = (rowStart % T) + tid;
    } else {
        int e = (rowStart - NS * T) / T;
        int l0 = (rowStart - NS * T) % T;
        int cnt = g_counts[e];
        if (l0 >= cnt) return;
        W = ew1 + (size_t)e * H * F;
        bias = eb1 + e * F;
        if (tid < BM) stok[tid] = (l0 + tid < cnt) ? g_perm[e * T + l0 + tid] : -1;
    }
    __syncthreads();

    char* dyn = (char*)(((uintptr_t)dynraw + 1023) & ~(uintptr_t)1023);
    uint32_t dyn32 = smem_u32(dyn);
    int n0 = blockIdx.x * BN;
    __nv_bfloat16* hh = (__nv_bfloat16*)g_scratch;
    __nv_bfloat16* hl = hh + (size_t)RTOT * F;

    const int NK = H / KTILE; // 16

    float4 la[2][2], lb[2][2];
    auto ldregs = [&](int it) {
        int k0 = it * KTILE;
#pragma unroll
        for (int q = 0; q < 2; q++) { // A: 128 rows x 8 groups of 8 floats
            int g = q * THREADS + tid;
            int row = g >> 3, grp = g & 7;
            int tok = stok[row];
            const float* src = x + (size_t)(tok >= 0 ? tok : 0) * H + k0 + grp * 8;
            la[q][0] = *(const float4*)src;
            la[q][1] = *(const float4*)(src + 4);
        }
#pragma unroll
        for (int q = 0; q < 2; q++) { // B: 64 k-rows x 16 groups of 8 floats
            int g = q * THREADS + tid;
            int row = g >> 4, grp = g & 15;
            const float* src = W + (size_t)(k0 + row) * F + n0 + grp * 8;
            lb[q][0] = *(const float4*)src;
            lb[q][1] = *(const float4*)(src + 4);
        }
    };
    auto cvst = [&](int s) {
        char* st = dyn + s * STAGE_BYTES;
#pragma unroll
        for (int q = 0; q < 2; q++) {
            int g = q * THREADS + tid;
            int row = g >> 3, grp = g & 7;
            uint32_t d = row * 128 + ((grp ^ (row & 7)) << 4);
            uint4 hi, lo;
            cvt8(la[q][0], la[q][1], hi, lo);
            *(uint4*)(st + OFF_AH + d) = hi;
            *(uint4*)(st + OFF_AL + d) = lo;
        }
#pragma unroll
        for (int q = 0; q < 2; q++) {
            int g = q * THREADS + tid;
            int row = g >> 4, grp = g & 15;
            int sub = grp >> 3, u = grp & 7;
            uint32_t d = sub * 16384 + row * 128 + ((u ^ (row & 7)) << 4);
            uint4 hi, lo;
            cvt8(lb[q][0], lb[q][1], hi, lo);
            *(uint4*)(st + OFF_B + d) = hi;
            *(uint4*)(st + OFF_B + 8192 + d) = lo;
        }
    };

    float acc[2][4][4];
#pragma unroll
    for (int a = 0; a < 2; a++)
#pragma unroll
        for (int b = 0; b < 4; b++)
#pragma unroll
            for (int c = 0; c < 4; c++) acc[a][b][c] = 0.0f;

    ldregs(0);
    cvst(0);
    ldregs(1);
    __syncthreads();

    for (int it = 0; it < NK; it++) {
        compute_stage(dyn32 + (it & 1) * STAGE_BYTES, wm, wn, lane, acc);
        if (it + 1 < NK) cvst((it + 1) & 1);
        __syncthreads();
        if (it + 2 < NK) ldregs(it + 2);
    }

    // Epilogue: bias + exact gelu + split -> hh/hl (warp tile 32x32)
    int lr = lane >> 2;
    int lc = (lane & 3) * 2;
#pragma unroll
    for (int mf = 0; mf < 2; mf++) {
#pragma unroll
        for (int half = 0; half < 2; half++) {
            int m = wm * 32 + mf * 16 + lr + half * 8;
            if (stok[m] < 0) continue;
            size_t rowbase = (size_t)(rowStart + m) * F;
#pragma unroll
            for (int j = 0; j < 4; j++) {
                int col = n0 + wn * 32 + j * 8 + lc;
                float v0 = gelu_exact(acc[mf][j][half * 2 + 0] + __ldg(&bias[col]));
                float v1 = gelu_exact(acc[mf][j][half * 2 + 1] + __ldg(&bias[col + 1]));
                __nv_bfloat16 h0, l0, h1, l1;
                split_bf16(v0, h0, l0);
                split_bf16(v1, h1, l1);
                *(uint32_t*)(hh + rowbase + col) = pack_bf16(h0, h1);
                *(uint32_t*)(hl + rowbase + col) = pack_bf16(l0, l1);
            }
        }
    }
}

// Tensor GEMM2: A from bf16 scratch, B = w2 fp32 split during staging.
__global__ void __launch_bounds__(THREADS, 1)
gemm2_kernel(const float* __restrict__ sw2, const float* __restrict__ sb2,
             const float* __restrict__ ew2, const float* __restrict__ eb2,
             float* __restrict__ out) {
    int rowStart = blockIdx.y * BM;
    int tid = threadIdx.x, wid = tid >> 5, lane = tid & 31;
    int wm = wid & 3, wn = wid >> 2;

    __shared__ int stok[BM];
    extern __shared__ char dynraw[];

    const float* W;
    const float* bias;
    if (rowStart < NS * T) {
        int slot = rowStart / T;
        W = sw2 + (size_t)slot * F * H;
        bias = sb2 + slot * H;
        if (tid < BM) stok[tid] = (rowStart % T) + tid;
    } else {
        int e = (rowStart - NS * T) / T;
        int l0 = (rowStart - NS * T) % T;
        int cnt = g_counts[e];
        if (l0 >= cnt) return;
        W = ew2 + (size_t)e * F * H;
        bias = eb2 + e * H;
        if (tid < BM) stok[tid] = (l0 + tid < cnt) ? g_perm[e * T + l0 + tid] : -1;
    }
    __syncthreads();

    char* dyn = (char*)(((uintptr_t)dynraw + 1023) & ~(uintptr_t)1023);
    uint32_t dyn32 = smem_u32(dyn);
    int n0 = blockIdx.x * BN;
    const __nv_bfloat16* hh = (const __nv_bfloat16*)g_scratch;
    const __nv_bfloat16* hl = hh + (size_t)RTOT * F;

    const int NK = F / KTILE; // 32

    uint4 lah[2], lal[2];
    float4 lb[2][2];
    auto ldregs = [&](int it) {
        int k0 = it * KTILE;
#pragma unroll
        for (int q = 0; q < 2; q++) {
            int g = q * THREADS + tid;
            int row = g >> 3, grp = g & 7;
            size_t o = (size_t)(rowStart + row) * F + k0 + grp * 8;
            lah[q] = *(const uint4*)(hh + o);
            lal[q] = *(const uint4*)(hl + o);
        }
#pragma unroll
        for (int q = 0; q < 2; q++) {
            int g = q * THREADS + tid;
            int row = g >> 4, grp = g & 15;
            const float* src = W + (size_t)(k0 + row) * H + n0 + grp * 8;
            lb[q][0] = *(const float4*)src;
            lb[q][1] = *(const float4*)(src + 4);
        }
    };
    auto cvst = [&](int s) {
        char* st = dyn + s * STAGE_BYTES;
#pragma unroll
        for (int q = 0; q < 2; q++) {
            int g = q * THREADS + tid;
            int row = g >> 3, grp = g & 7;
            uint32_t d = row * 128 + ((grp ^ (row & 7)) << 4);
            *(uint4*)(st + OFF_AH + d) = lah[q];
            *(uint4*)(st + OFF_AL + d) = lal[q];
        }
#pragma unroll
        for (int q = 0; q < 2; q++) {
            int g = q * THREADS + tid;
            int row = g >> 4, grp = g & 15;
            int sub = grp >> 3, u = grp & 7;
            uint32_t d = sub * 16384 + row * 128 + ((u ^ (row & 7)) << 4);
            uint4 hi, lo;
            cvt8(lb[q][0], lb[q][1], hi, lo);
            *(uint4*)(st + OFF_B + d) = hi;
            *(uint4*)(st + OFF_B + 8192 + d) = lo;
        }
    };

    float acc[2][4][4];
#pragma unroll
    for (int a = 0; a < 2; a++)
#pragma unroll
        for (int b = 0; b < 4; b++)
#pragma unroll
            for (int c = 0; c < 4; c++) acc[a][b][c] = 0.0f;

    ldregs(0);
    cvst(0);
    ldregs(1);
    __syncthreads();

    for (int it = 0; it < NK; it++) {
        compute_stage(dyn32 + (it & 1) * STAGE_BYTES, wm, wn, lane, acc);
        if (it + 1 < NK) cvst((it + 1) & 1);
        __syncthreads();
        if (it + 2 < NK) ldregs(it + 2);
    }

    int lr = lane >> 2;
    int lc = (lane & 3) * 2;
#pragma unroll
    for (int mf = 0; mf < 2; mf++) {
#pragma unroll
        for (int half = 0; half < 2; half++) {
            int m = wm * 32 + mf * 16 + lr + half * 8;
            int tok = stok[m];
            if (tok < 0) continue;
            float* dst = out + (size_t)tok * H;
#pragma unroll
            for (int j = 0; j < 4; j++) {
                int col = n0 + wn * 32 + j * 8 + lc;
                atomicAdd(dst + col, acc[mf][j][half * 2 + 0] + __ldg(&bias[col]));
                atomicAdd(dst + col + 1, acc[mf][j][half * 2 + 1] + __ldg(&bias[col + 1]));
            }
        }
    }
}

// ---------------------------------------------------------------------------
// Fallback SIMT kernels (round-1 design; hf aliases g_scratch)
__global__ void __launch_bounds__(256, 2)
fb_gemm1_kernel(const float* __restrict__ x,
                const float* __restrict__ sw1, const float* __restrict__ sb1,
                const float* __restrict__ ew1, const float* __restrict__ eb1) {
    float* hf = (float*)g_scratch;
    int rowStart = blockIdx.y * FBM;
    int tid = threadIdx.x;
    __shared__ int stok[FBM];
    __shared__ float As[FBK][FBM + 1];
    __shared__ float Bs[FBK][FBN];

    const float* W;
    const float* bias;
    if (rowStart < NS * T) {
        int slot = rowStart / T;
        W = sw1 + (size_t)slot * H * F;
        bias = sb1 + slot * F;
        if (tid < FBM) stok[tid] = (rowStart % T) + tid;
    } else {
        int e = (rowStart - NS * T) / T;
        int l0 = (rowStart - NS * T) % T;
        int cnt = g_counts[e];
        if (l0 >= cnt) return;
        W = ew1 + (size_t)e * H * F;
        bias = eb1 + e * F;
        if (tid < FBM) stok[tid] = (l0 + tid < cnt) ? g_perm[e * T + l0 + tid] : -1;
    }
    __syncthreads();

    int n0 = blockIdx.x * FBN;
    int ty = tid / 16, tx = tid % 16;
    float acc[4][4];
#pragma unroll
    for (int i = 0; i < 4; i++)
#pragma unroll
        for (int j = 0; j < 4; j++) acc[i][j] = 0.0f;

    int ar = tid / 8, ak = (tid % 8) * 4;
    int br = tid / 16, bn = (tid % 16) * 4;

    for (int k0 = 0; k0 < H; k0 += FBK) {
#pragma unroll
        for (int p = 0; p < 2; p++) {
            int r = ar + p * 32;
            int tok = stok[r];
            float4 v = make_float4(0.f, 0.f, 0.f, 0.f);
            if (tok >= 0) v = *(const float4*)(x + (size_t)tok * H + k0 + ak);
            As[ak + 0][r] = v.x; As[ak + 1][r] = v.y;
            As[ak + 2][r] = v.z; As[ak + 3][r] = v.w;
        }
#pragma unroll
        for (int p = 0; p < 2; p++) {
            int kk = br + p * 16;
            *(float4*)&Bs[kk][bn] = *(const float4*)(W + (size_t)(k0 + kk) * F + n0 + bn);
        }
        __syncthreads();
#pragma unroll
        for (int kk = 0; kk < FBK; kk++) {
            float a[4];
#pragma unroll
            for (int i = 0; i < 4; i++) a[i] = As[kk][ty * 4 + i];
            float4 b = *(const float4*)&Bs[kk][tx * 4];
#pragma unroll
            for (int i = 0; i < 4; i++) {
                acc[i][0] += a[i] * b.x; acc[i][1] += a[i] * b.y;
                acc[i][2] += a[i] * b.z; acc[i][3] += a[i] * b.w;
            }
        }
        __syncthreads();
    }

#pragma unroll
    for (int i = 0; i < 4; i++) {
        int r = ty * 4 + i;
        if (stok[r] < 0) continue;
        size_t base = (size_t)(rowStart + r) * F + n0 + tx * 4;
#pragma unroll
        for (int j = 0; j < 4; j++) {
            float v = acc[i][j] + bias[n0 + tx * 4 + j];
            hf[base + j] = gelu_exact(v);
        }
    }
}

__global__ void __launch_bounds__(256, 2)
fb_gemm2_kernel(const float* __restrict__ sw2, const float* __restrict__ sb2,
                const float* __restrict__ ew2, const float* __restrict__ eb2,
                float* __restrict__ out) {
    const float* hf = (const float*)g_scratch;
    int rowStart = blockIdx.y * FBM;
    int tid = threadIdx.x;
    __shared__ int stok[FBM];
    __shared__ float As[FBK][FBM + 1];
    __shared__ float Bs[FBK][FBN];

    const float* W;
    const float* bias;
    if (rowStart < NS * T) {
        int slot = rowStart / T;
        W = sw2 + (size_t)slot * F * H;
        bias = sb2 + slot * H;
        if (tid < FBM) stok[tid] = (rowStart % T) + tid;
    } else {
        int e = (rowStart - NS * T) / T;
        int l0 = (rowStart - NS * T) % T;
        int cnt = g_counts[e];
        if (l0 >= cnt) return;
        W = ew2 + (size_t)e * F * H;
        bias = eb2 + e * H;
        if (tid < FBM) stok[tid] = (l0 + tid < cnt) ? g_perm[e * T + l0 + tid] : -1;
    }
    __syncthreads();

    int n0 = blockIdx.x * FBN;
    int ty = tid / 16, tx = tid % 16;
    float acc[4][4];
#pragma unroll
    for (int i = 0; i < 4; i++)
#pragma unroll
        for (int j = 0; j < 4; j++) acc[i][j] = 0.0f;

    int ar = tid / 8, ak = (tid % 8) * 4;
    int br = tid / 16, bn = (tid % 16) * 4;

    for (int k0 = 0; k0 < F; k0 += FBK) {
#pragma unroll
        for (int p = 0; p < 2; p++) {
            int r = ar + p * 32;
            float4 v = *(const float4*)(hf + (size_t)(rowStart + r) * F + k0 + ak);
            As[ak + 0][r] = v.x; As[ak + 1][r] = v.y;
            As[ak + 2][r] = v.z; As[ak + 3][r] = v.w;
        }
#pragma unroll
        for (int p = 0; p < 2; p++) {
            int kk = br + p * 16;
            *(float4*)&Bs[kk][bn] = *(const float4*)(W + (size_t)(k0 + kk) * H + n0 + bn);
        }
        __syncthreads();
#pragma unroll
        for (int kk = 0; kk < FBK; kk++) {
            float a[4];
#pragma unroll
            for (int i = 0; i < 4; i++) a[i] = As[kk][ty * 4 + i];
            float4 b = *(const float4*)&Bs[kk][tx * 4];
#pragma unroll
            for (int i = 0; i < 4; i++) {
                acc[i][0] += a[i] * b.x; acc[i][1] += a[i] * b.y;
                acc[i][2] += a[i] * b.z; acc[i][3] += a[i] * b.w;
            }
        }
        __syncthreads();
    }

#pragma unroll
    for (int i = 0; i < 4; i++) {
        int r = ty * 4 + i;
        int tok = stok[r];
        if (tok < 0) continue;
        float* dst = out + (size_t)tok * H + n0 + tx * 4;
#pragma unroll
        for (int j = 0; j < 4; j++) {
            atomicAdd(dst + j, acc[i][j] + bias[n0 + tx * 4 + j]);
        }
    }
}

// ---------------------------------------------------------------------------
static void launch_fallback(const float* x,
                            const float* sw1, const float* sb1,
                            const float* sw2, const float* sb2,
                            const float* ew1, const float* eb1,
                            const float* ew2, const float* eb2,
                            float* out) {
    dim3 g1(F / FBN, RTOT / FBM);
    fb_gemm1_kernel<<<g1, 256>>>(x, sw1, sb1, ew1, eb1);
    dim3 g2(H / FBN, RTOT / FBM);
    fb_gemm2_kernel<<<g2, 256>>>(sw2, sb2, ew2, eb2, out);
}

extern "C" void kernel_launch(void* const* d_in, const int* in_sizes, int n_in,
                              void* d_out, int out_size) {
    const float* x   = (const float*)d_in[0];
    const float* sw1 = (const float*)d_in[1];
    const float* sb1 = (const float*)d_in[2];
    const float* sw2 = (const float*)d_in[3];
    const float* sb2 = (const float*)d_in[4];
    const float* ew1 = (const float*)d_in[5];
    const float* eb1 = (const float*)d_in[6];
    const float* ew2 = (const float*)d_in[7];
    const float* eb2 = (const float*)d_in[8];
    const float* rw  = (const float*)d_in[9];
    const float* rb  = (const float*)d_in[10];
    float* out = (float*)d_out;

    bool tensor_ok = true;
    if (cudaFuncSetAttribute(gemm1_kernel, cudaFuncAttributeMaxDynamicSharedMemorySize,
                             DYN_BYTES) != cudaSuccess) tensor_ok = false;
    if (cudaFuncSetAttribute(gemm2_kernel, cudaFuncAttributeMaxDynamicSharedMemorySize,
                             DYN_BYTES) != cudaSuccess) tensor_ok = false;

    zero_kernel<<<(T * H + 255) / 256, 256>>>(out);
    router_kernel<<<T, 256>>>(x, rw, rb);

    if (tensor_ok) {
        (void)cudaGetLastError(); // clear before the tensor chain
        dim3 g1(F / BN, RTOT / BM); // 16 x 320
        gemm1_kernel<<<g1, THREADS, DYN_BYTES>>>(x, sw1, sb1, ew1, eb1);
        dim3 g2(H / BN, RTOT / BM); // 8 x 320
        gemm2_kernel<<<g2, THREADS, DYN_BYTES>>>(sw2, sb2, ew2, eb2, out);
        if (cudaGetLastError() != cudaSuccess) {
            // Launch-config failure: tensor gemms contributed nothing real;
            // recompute with the proven SIMT path (hf aliases the same scratch).
            launch_fallback(x, sw1, sb1, sw2, sb2, ew1, eb1, ew2, eb2, out);
        }
    } else {
        launch_fallback(x, sw1, sb1, sw2, sb2, ew1, eb1, ew2, eb2, out);
    }
}